// round 6
// baseline (speedup 1.0000x reference)
#include <cuda_runtime.h>
#include <cuda_bf16.h>
#include <math.h>
#include <stdint.h>

// ---------------- problem constants ----------------
constexpr int   BN      = 8192;
constexpr int   DD      = 256;
constexpr int   NS      = 64;
constexpr float INV_TAU = 1.0f / 0.07f;
constexpr float MARGIN  = 0.2f;
constexpr int   BK      = 32;          // bf16 per K-chunk
constexpr int   NIT     = DD / BK;     // 8
// CTA tile: 128 rows x 64 cols, 8 warps (4m x 2n), warp tile 32x32

// ---------------- device scratch ----------------
__device__ __align__(16) __nv_bfloat16 g_Abf[(size_t)BN * DD];
__device__ __align__(16) __nv_bfloat16 g_Bbf[(size_t)BN * DD];

__device__ float g_rowexp[BN];
__device__ float g_colexp[BN];
__device__ float g_rowsum[BN];
__device__ float g_rowsame[BN];
__device__ float g_diag[BN];
__device__ float g_cnt[NS];
__device__ float g_segv[NS];
__device__ float g_segt[NS];
__device__ float g_tri[2];

constexpr int N_ZERO = 5 * BN + 3 * NS + 2;

__global__ void zero_kernel() {
    int i = blockIdx.x * blockDim.x + threadIdx.x;
    int stride = gridDim.x * blockDim.x;
    for (; i < N_ZERO; i += stride) {
        if (i < BN)            g_rowexp[i] = 0.f;
        else if (i < 2 * BN)   g_colexp[i - BN] = 0.f;
        else if (i < 3 * BN)   g_rowsum[i - 2 * BN] = 0.f;
        else if (i < 4 * BN)   g_rowsame[i - 3 * BN] = 0.f;
        else if (i < 5 * BN)   g_diag[i - 4 * BN] = 0.f;
        else {
            int j = i - 5 * BN;
            if (j < NS)            g_cnt[j] = 0.f;
            else if (j < 2 * NS)   g_segv[j - NS] = 0.f;
            else if (j < 3 * NS)   g_segt[j - 2 * NS] = 0.f;
            else                   g_tri[j - 3 * NS] = 0.f;
        }
    }
}

// ---------------- fp32 -> bf16 ----------------
__global__ void convert_kernel(const float* __restrict__ A,
                               const float* __restrict__ B) {
    int idx = blockIdx.x * blockDim.x + threadIdx.x;   // one thread per 4 elems
    int total = BN * DD / 4;
    if (idx >= total) return;
    size_t base = (size_t)idx * 4;
    float4 a = *(const float4*)&A[base];
    float4 b = *(const float4*)&B[base];
    *(__nv_bfloat162*)&g_Abf[base]     = __floats2bfloat162_rn(a.x, a.y);
    *(__nv_bfloat162*)&g_Abf[base + 2] = __floats2bfloat162_rn(a.z, a.w);
    *(__nv_bfloat162*)&g_Bbf[base]     = __floats2bfloat162_rn(b.x, b.y);
    *(__nv_bfloat162*)&g_Bbf[base + 2] = __floats2bfloat162_rn(b.z, b.w);
}

// ---------------- diag (exact fp32) + species counts ----------------
__global__ void diag_count_kernel(const float* __restrict__ S,
                                  const float* __restrict__ T,
                                  const int* __restrict__ ids) {
    int warp = threadIdx.x >> 5;
    int lane = threadIdx.x & 31;
    int row = blockIdx.x * 8 + warp;
    if (row >= BN) return;
    const float* sr = S + (size_t)row * DD;
    const float* tr = T + (size_t)row * DD;
    float acc = 0.f;
    #pragma unroll
    for (int k = lane; k < DD; k += 32)
        acc += sr[k] * tr[k];
    #pragma unroll
    for (int o = 16; o > 0; o >>= 1)
        acc += __shfl_xor_sync(0xffffffffu, acc, o);
    if (lane == 0) {
        g_diag[row] = acc;
        atomicAdd(&g_cnt[ids[row]], 1.0f);
    }
}

// ---------------- PTX helpers ----------------
__device__ __forceinline__ uint32_t smem_u32(const void* p) {
    uint32_t a;
    asm("{ .reg .u64 t; cvta.to.shared.u64 t, %1; cvt.u32.u64 %0, t; }"
        : "=r"(a) : "l"(p));
    return a;
}
__device__ __forceinline__ void cp16(uint32_t dst, const void* src) {
    asm volatile("cp.async.cg.shared.global [%0], [%1], 16;" :: "r"(dst), "l"(src));
}
template<int N> __device__ __forceinline__ void cp_wait() {
    asm volatile("cp.async.wait_group %0;" :: "n"(N) : "memory");
}
__device__ __forceinline__ void ldsm_x4(uint32_t* r, uint32_t addr) {
    asm volatile("ldmatrix.sync.aligned.m8n8.x4.shared.b16 {%0,%1,%2,%3}, [%4];"
                 : "=r"(r[0]), "=r"(r[1]), "=r"(r[2]), "=r"(r[3]) : "r"(addr));
}
__device__ __forceinline__ void mma16816(float* d, const uint32_t* a, const uint32_t* b) {
    asm volatile(
        "mma.sync.aligned.m16n8k16.row.col.f32.bf16.bf16.f32 "
        "{%0,%1,%2,%3}, {%4,%5,%6,%7}, {%8,%9}, {%0,%1,%2,%3};"
        : "+f"(d[0]), "+f"(d[1]), "+f"(d[2]), "+f"(d[3])
        : "r"(a[0]), "r"(a[1]), "r"(a[2]), "r"(a[3]), "r"(b[0]), "r"(b[1]));
}

// swizzled byte offset within a [rows x 64B] stage tile
__device__ __forceinline__ uint32_t swz(int r, int q) {
    return (uint32_t)(r * 64 + ((q ^ ((r >> 1) & 3)) << 4));
}

// dynamic smem layout (bytes): 4 stages of (A 8KB + B 4KB), then stats
constexpr int STG     = 12288;
constexpr int ST_OFF  = 4 * STG;                 // 49152
constexpr int SMEM_DYN = ST_OFF + 3 * 512 + 2 * 256;   // 51200

// ---------------- main bf16 mma.sync GEMM + fused epilogue ----------------
__global__ void __launch_bounds__(256, 3)
gemm_kernel(const int* __restrict__ ids) {
    extern __shared__ char smem[];
    const uint32_t sbase = smem_u32(smem);
    float* s_rexp  = (float*)(smem + ST_OFF);
    float* s_rsum  = (float*)(smem + ST_OFF + 512);
    float* s_rsame = (float*)(smem + ST_OFF + 1024);
    float* s_cexp  = (float*)(smem + ST_OFF + 1536);   // 64 floats
    int*   s_idc   = (int*)  (smem + ST_OFF + 1792);   // 64 ints

    const int tid  = threadIdx.x;
    const int wid  = tid >> 5;
    const int lane = tid & 31;
    const int wm   = wid & 3;        // warp m index (4)
    const int wn   = wid >> 2;       // warp n index (2)
    const int row0 = blockIdx.y * 128;
    const int col0 = blockIdx.x * 64;

    if (tid < 128) {
        s_rexp[tid] = 0.f; s_rsum[tid] = 0.f; s_rsame[tid] = 0.f;
        if (tid < 64) { s_cexp[tid] = 0.f; s_idc[tid] = ids[col0 + tid]; }
    }

    // hoisted swizzled ldmatrix addresses (per ks half, within a stage tile)
    uint32_t aaddr[2][2], baddr[2][2];
    #pragma unroll
    for (int ks = 0; ks < 2; ks++) {
        #pragma unroll
        for (int mt = 0; mt < 2; mt++)
            aaddr[ks][mt] = swz(wm * 32 + mt * 16 + (lane & 15),
                                ks * 2 + (lane >> 4));
        #pragma unroll
        for (int g = 0; g < 2; g++)
            baddr[ks][g] = swz(wn * 32 + (2 * g + ((lane >> 4) & 1)) * 8 + (lane & 7),
                               ks * 2 + ((lane >> 3) & 1));
    }

    float acc[2][4][4];
    #pragma unroll
    for (int mt = 0; mt < 2; mt++)
        #pragma unroll
        for (int nt = 0; nt < 4; nt++)
            #pragma unroll
            for (int c = 0; c < 4; c++) acc[mt][nt][c] = 0.f;

    // ---- async load of one K-chunk into stage slot ----
    auto load_stage = [&](int slot, int it) {
        const int kb = it * BK;
        const uint32_t sA = sbase + slot * STG;
        const uint32_t sB = sA + 8192;
        // A: 128 rows x 64B -> 512 x cp16; 2 per thread
        #pragma unroll
        for (int h = 0; h < 2; h++) {
            int f = tid + h * 256;
            int r = f >> 2, q = f & 3;
            cp16(sA + swz(r, q), &g_Abf[(size_t)(row0 + r) * DD + kb + q * 8]);
        }
        // B: 64 rows x 64B -> 256 x cp16; 1 per thread
        {
            int r = tid >> 2, q = tid & 3;
            cp16(sB + swz(r, q), &g_Bbf[(size_t)(col0 + r) * DD + kb + q * 8]);
        }
        asm volatile("cp.async.commit_group;");
    };

    load_stage(0, 0);
    load_stage(1, 1);
    load_stage(2, 2);

    #pragma unroll
    for (int it = 0; it < NIT; it++) {
        if (it < NIT - 2)      cp_wait<2>();
        else if (it == NIT - 2) cp_wait<1>();
        else                    cp_wait<0>();
        __syncthreads();
        if (it + 3 < NIT) load_stage((it + 3) & 3, it + 3);

        const uint32_t sA = sbase + (it & 3) * STG;
        const uint32_t sB = sA + 8192;
        #pragma unroll
        for (int ks = 0; ks < 2; ks++) {
            uint32_t a[2][4], b[4][2];
            #pragma unroll
            for (int mt = 0; mt < 2; mt++)
                ldsm_x4(a[mt], sA + aaddr[ks][mt]);
            #pragma unroll
            for (int g = 0; g < 2; g++)
                ldsm_x4(&b[2 * g][0], sB + baddr[ks][g]);   // fills b[2g], b[2g+1]
            #pragma unroll
            for (int mt = 0; mt < 2; mt++)
                #pragma unroll
                for (int nt = 0; nt < 4; nt++)
                    mma16816(acc[mt][nt], a[mt], b[nt]);
        }
    }
    __syncthreads();

    // ---- epilogue: fragment -> row/col stats (exact fp32 diagonal patch) ----
    #pragma unroll
    for (int mt = 0; mt < 2; mt++) {
        #pragma unroll
        for (int h = 0; h < 2; h++) {
            const int rloc = wm * 32 + mt * 16 + (lane >> 2) + 8 * h;
            const int grow = row0 + rloc;
            const int rid  = ids[grow];
            const float dval = g_diag[grow];
            float rs = 0.f, rsm = 0.f, re = 0.f;
            #pragma unroll
            for (int nt = 0; nt < 4; nt++) {
                #pragma unroll
                for (int cc = 0; cc < 2; cc++) {
                    float s = acc[mt][nt][2 * h + cc];
                    int cloc = wn * 32 + nt * 8 + (lane & 3) * 2 + cc;
                    if (rid == s_idc[cloc]) {
                        if (grow == col0 + cloc) s = dval;   // exact diagonal
                        rsm += s;
                        float e = __expf((s - 1.0f) * INV_TAU);
                        re += e;
                        atomicAdd(&s_cexp[cloc], e);
                    }
                    rs += s;
                }
            }
            atomicAdd(&s_rexp[rloc],  re);
            atomicAdd(&s_rsum[rloc],  rs);
            atomicAdd(&s_rsame[rloc], rsm);
        }
    }
    __syncthreads();

    if (tid < 128) {
        atomicAdd(&g_rowexp[row0 + tid],  s_rexp[tid]);
        atomicAdd(&g_rowsum[row0 + tid],  s_rsum[tid]);
        atomicAdd(&g_rowsame[row0 + tid], s_rsame[tid]);
        if (tid < 64) atomicAdd(&g_colexp[col0 + tid], s_cexp[tid]);
    }
}

// ---------------- per-row CE, segment sums, triplet (block-reduced) ----------------
__global__ void finalize_kernel(const int* __restrict__ ids) {
    __shared__ float sh_segv[NS];
    __shared__ float sh_segt[NS];
    const int tid = threadIdx.x;
    if (tid < NS) { sh_segv[tid] = 0.f; sh_segt[tid] = 0.f; }
    __syncthreads();

    int i = blockIdx.x * blockDim.x + tid;
    float tri_v = 0.f, tri_n = 0.f;
    if (i < BN) {
        int id = ids[i];
        float dl = g_diag[i] * INV_TAU;
        float cev = logf(g_rowexp[i]) + INV_TAU - dl;
        float cet = logf(g_colexp[i]) + INV_TAU - dl;
        atomicAdd(&sh_segv[id], cev);
        atomicAdd(&sh_segt[id], cet);

        float cnt = g_cnt[id];
        float pos_cnt = cnt - 1.0f;
        float neg_cnt = (float)BN - cnt;
        float pos_mean = (g_rowsame[i] - g_diag[i]) / fmaxf(pos_cnt, 1.0f);
        float neg_mean = (g_rowsum[i] - g_rowsame[i]) / fmaxf(neg_cnt, 1.0f);
        float tri = fmaxf(neg_mean - pos_mean + MARGIN, 0.0f);
        bool valid = (pos_cnt > 0.0f) && (neg_cnt > 0.0f);
        tri_v = valid ? tri : 0.0f;
        tri_n = valid ? 1.0f : 0.0f;
    }
    #pragma unroll
    for (int o = 16; o > 0; o >>= 1) {
        tri_v += __shfl_xor_sync(0xffffffffu, tri_v, o);
        tri_n += __shfl_xor_sync(0xffffffffu, tri_n, o);
    }
    if ((tid & 31) == 0) {
        atomicAdd(&g_tri[0], tri_v);
        atomicAdd(&g_tri[1], tri_n);
    }
    __syncthreads();
    if (tid < NS) {
        atomicAdd(&g_segv[tid], sh_segv[tid]);
        atomicAdd(&g_segt[tid], sh_segt[tid]);
    }
}

__global__ void combine_kernel(float* __restrict__ out) {
    __shared__ float sv[NS], sn[NS];
    int s = threadIdx.x;
    float cnt = g_cnt[s];
    bool valid = cnt >= 2.0f;
    float per = (g_segv[s] + g_segt[s]) / (2.0f * fmaxf(cnt, 1.0f));
    sv[s] = valid ? per : 0.0f;
    sn[s] = valid ? 1.0f : 0.0f;
    __syncthreads();
    if (s == 0) {
        float S = 0.f, N = 0.f;
        for (int i = 0; i < NS; i++) { S += sv[i]; N += sn[i]; }
        float loss_infonce = S / fmaxf(N, 1.0f);
        float loss_triplet = g_tri[0] / fmaxf(g_tri[1], 1.0f);
        out[0] = loss_infonce + loss_triplet;
    }
}

extern "C" void kernel_launch(void* const* d_in, const int* in_sizes, int n_in,
                              void* d_out, int out_size) {
    const float* species = (const float*)d_in[0];
    const float* text    = (const float*)d_in[1];
    const int*   ids     = (const int*)d_in[2];
    float* out = (float*)d_out;

    cudaFuncSetAttribute(gemm_kernel,
                         cudaFuncAttributeMaxDynamicSharedMemorySize, SMEM_DYN);

    zero_kernel<<<82, 512>>>();
    convert_kernel<<<(BN * DD / 4 + 255) / 256, 256>>>(species, text);
    diag_count_kernel<<<BN / 8, 256>>>(species, text, ids);
    dim3 grid(BN / 64, BN / 128);
    gemm_kernel<<<grid, 256, SMEM_DYN>>>(ids);
    finalize_kernel<<<BN / 256, 256>>>(ids);
    combine_kernel<<<1, NS>>>(out);
}

// round 8
// speedup vs baseline: 1.0741x; 1.0741x over previous
#include <cuda_runtime.h>
#include <cuda_bf16.h>
#include <math.h>
#include <stdint.h>

// ---------------- problem constants ----------------
constexpr int   BN      = 8192;
constexpr int   DD      = 256;
constexpr int   NS      = 64;
constexpr float INV_TAU = 1.0f / 0.07f;
constexpr float MARGIN  = 0.2f;
constexpr int   BK      = 64;          // bf16 per K-chunk (128 bytes)
constexpr int   NIT     = DD / BK;     // 4
constexpr int   STAGES  = 3;
// CTA tile: 128 x 128, 8 warps (4m x 2n), warp tile 32x64

// ---------------- device scratch ----------------
__device__ __align__(16) __nv_bfloat16 g_Abf[(size_t)BN * DD];
__device__ __align__(16) __nv_bfloat16 g_Bbf[(size_t)BN * DD];

__device__ float g_rowexp[BN];
__device__ float g_colexp[BN];
__device__ float g_rowsum[BN];
__device__ float g_rowsame[BN];
__device__ float g_diag[BN];
__device__ float g_cnt[NS];
__device__ float g_segv[NS];
__device__ float g_segt[NS];
__device__ float g_tri[2];

constexpr int N_ZERO = 5 * BN + 3 * NS + 2;

__global__ void zero_kernel() {
    int i = blockIdx.x * blockDim.x + threadIdx.x;
    int stride = gridDim.x * blockDim.x;
    for (; i < N_ZERO; i += stride) {
        if (i < BN)            g_rowexp[i] = 0.f;
        else if (i < 2 * BN)   g_colexp[i - BN] = 0.f;
        else if (i < 3 * BN)   g_rowsum[i - 2 * BN] = 0.f;
        else if (i < 4 * BN)   g_rowsame[i - 3 * BN] = 0.f;
        else if (i < 5 * BN)   g_diag[i - 4 * BN] = 0.f;
        else {
            int j = i - 5 * BN;
            if (j < NS)            g_cnt[j] = 0.f;
            else if (j < 2 * NS)   g_segv[j - NS] = 0.f;
            else if (j < 3 * NS)   g_segt[j - 2 * NS] = 0.f;
            else                   g_tri[j - 3 * NS] = 0.f;
        }
    }
}

// ---------------- fp32 -> bf16 ----------------
__global__ void convert_kernel(const float* __restrict__ A,
                               const float* __restrict__ B) {
    int idx = blockIdx.x * blockDim.x + threadIdx.x;   // one thread per 4 elems
    int total = BN * DD / 4;
    if (idx >= total) return;
    size_t base = (size_t)idx * 4;
    float4 a = *(const float4*)&A[base];
    float4 b = *(const float4*)&B[base];
    *(__nv_bfloat162*)&g_Abf[base]     = __floats2bfloat162_rn(a.x, a.y);
    *(__nv_bfloat162*)&g_Abf[base + 2] = __floats2bfloat162_rn(a.z, a.w);
    *(__nv_bfloat162*)&g_Bbf[base]     = __floats2bfloat162_rn(b.x, b.y);
    *(__nv_bfloat162*)&g_Bbf[base + 2] = __floats2bfloat162_rn(b.z, b.w);
}

// ---------------- diag (exact fp32) + species counts ----------------
__global__ void diag_count_kernel(const float* __restrict__ S,
                                  const float* __restrict__ T,
                                  const int* __restrict__ ids) {
    int warp = threadIdx.x >> 5;
    int lane = threadIdx.x & 31;
    int row = blockIdx.x * 8 + warp;
    if (row >= BN) return;
    const float* sr = S + (size_t)row * DD;
    const float* tr = T + (size_t)row * DD;
    float acc = 0.f;
    #pragma unroll
    for (int k = lane; k < DD; k += 32)
        acc += sr[k] * tr[k];
    #pragma unroll
    for (int o = 16; o > 0; o >>= 1)
        acc += __shfl_xor_sync(0xffffffffu, acc, o);
    if (lane == 0) {
        g_diag[row] = acc;
        atomicAdd(&g_cnt[ids[row]], 1.0f);
    }
}

// ---------------- PTX helpers ----------------
__device__ __forceinline__ uint32_t smem_u32(const void* p) {
    uint32_t a;
    asm("{ .reg .u64 t; cvta.to.shared.u64 t, %1; cvt.u32.u64 %0, t; }"
        : "=r"(a) : "l"(p));
    return a;
}
__device__ __forceinline__ void cp16(uint32_t dst, const void* src) {
    asm volatile("cp.async.cg.shared.global [%0], [%1], 16;" :: "r"(dst), "l"(src));
}
template<int N> __device__ __forceinline__ void cp_wait() {
    asm volatile("cp.async.wait_group %0;" :: "n"(N) : "memory");
}
__device__ __forceinline__ void ldsm_x4(uint32_t* r, uint32_t addr) {
    asm volatile("ldmatrix.sync.aligned.m8n8.x4.shared.b16 {%0,%1,%2,%3}, [%4];"
                 : "=r"(r[0]), "=r"(r[1]), "=r"(r[2]), "=r"(r[3]) : "r"(addr));
}
__device__ __forceinline__ void mma16816(float* d, const uint32_t* a, const uint32_t* b) {
    asm volatile(
        "mma.sync.aligned.m16n8k16.row.col.f32.bf16.bf16.f32 "
        "{%0,%1,%2,%3}, {%4,%5,%6,%7}, {%8,%9}, {%0,%1,%2,%3};"
        : "+f"(d[0]), "+f"(d[1]), "+f"(d[2]), "+f"(d[3])
        : "r"(a[0]), "r"(a[1]), "r"(a[2]), "r"(a[3]), "r"(b[0]), "r"(b[1]));
}

// SW128 swizzle: [rows x 128B] tile; r = row, q = 16B chunk (0..7)
__device__ __forceinline__ uint32_t swz(int r, int q) {
    return (uint32_t)(r * 128 + ((q ^ (r & 7)) << 4));
}

// dynamic smem layout (bytes): 3 stages of (A 16KB + B 16KB), then stats
constexpr int STG     = 32768;
constexpr int ST_OFF  = STAGES * STG;                  // 98304
constexpr int SMEM_DYN = ST_OFF + 5 * 512;             // 100864

// ---------------- main bf16 mma.sync GEMM + fused epilogue ----------------
__global__ void __launch_bounds__(256, 2)
gemm_kernel(const int* __restrict__ ids) {
    extern __shared__ char smem[];
    const uint32_t sbase = smem_u32(smem);
    float* s_rexp  = (float*)(smem + ST_OFF);
    float* s_rsum  = (float*)(smem + ST_OFF + 512);
    float* s_rsame = (float*)(smem + ST_OFF + 1024);
    float* s_cexp  = (float*)(smem + ST_OFF + 1536);
    int*   s_idc   = (int*)  (smem + ST_OFF + 2048);

    const int tid  = threadIdx.x;
    const int wid  = tid >> 5;
    const int lane = tid & 31;
    const int wm   = wid & 3;        // warp m index (4)
    const int wn   = wid >> 2;       // warp n index (2)
    const int row0 = blockIdx.y * 128;
    const int col0 = blockIdx.x * 128;

    if (tid < 128) {
        s_rexp[tid] = 0.f; s_rsum[tid] = 0.f; s_rsame[tid] = 0.f; s_cexp[tid] = 0.f;
        s_idc[tid] = ids[col0 + tid];
    }

    // hoisted swizzled ldmatrix addresses (per ks quarter, within a stage tile)
    uint32_t aaddr[4][2], baddr[4][4];
    #pragma unroll
    for (int ks = 0; ks < 4; ks++) {
        #pragma unroll
        for (int mt = 0; mt < 2; mt++)
            aaddr[ks][mt] = swz(wm * 32 + mt * 16 + (lane & 15),
                                ks * 2 + (lane >> 4));
        #pragma unroll
        for (int np = 0; np < 4; np++)
            baddr[ks][np] = swz(wn * 64 + np * 16 + ((lane >> 4) & 1) * 8 + (lane & 7),
                                ks * 2 + ((lane >> 3) & 1));
    }

    float acc[2][8][4];
    #pragma unroll
    for (int mt = 0; mt < 2; mt++)
        #pragma unroll
        for (int nt = 0; nt < 8; nt++)
            #pragma unroll
            for (int c = 0; c < 4; c++) acc[mt][nt][c] = 0.f;

    // ---- async load of one K-chunk (64 bf16 = 128B per row) into stage slot ----
    auto load_stage = [&](int slot, int it) {
        const int kb = it * BK;
        const uint32_t sA = sbase + slot * STG;
        const uint32_t sB = sA + 16384;
        #pragma unroll
        for (int h = 0; h < 4; h++) {
            int f = tid + h * 256;       // 0..1023
            int r = f >> 3, q = f & 7;
            uint32_t sw = swz(r, q);
            cp16(sA + sw, &g_Abf[(size_t)(row0 + r) * DD + kb + q * 8]);
            cp16(sB + sw, &g_Bbf[(size_t)(col0 + r) * DD + kb + q * 8]);
        }
        asm volatile("cp.async.commit_group;");
    };

    load_stage(0, 0);
    load_stage(1, 1);

    #pragma unroll
    for (int it = 0; it < NIT; it++) {
        if (it + 1 < NIT) cp_wait<1>();
        else              cp_wait<0>();
        __syncthreads();
        if (it + 2 < NIT) load_stage((it + 2) % STAGES, it + 2);

        const uint32_t sA = sbase + (it % STAGES) * STG;
        const uint32_t sB = sA + 16384;
        #pragma unroll
        for (int ks = 0; ks < 4; ks++) {
            uint32_t a[2][4], b[8][2];
            #pragma unroll
            for (int mt = 0; mt < 2; mt++)
                ldsm_x4(a[mt], sA + aaddr[ks][mt]);
            #pragma unroll
            for (int np = 0; np < 4; np++)
                ldsm_x4(&b[2 * np][0], sB + baddr[ks][np]);   // fills b[2np], b[2np+1]
            #pragma unroll
            for (int mt = 0; mt < 2; mt++)
                #pragma unroll
                for (int nt = 0; nt < 8; nt++)
                    mma16816(acc[mt][nt], a[mt], b[nt]);
        }
    }
    __syncthreads();

    // ---- epilogue: fragment -> row/col stats (exact fp32 diagonal patch) ----
    #pragma unroll
    for (int mt = 0; mt < 2; mt++) {
        #pragma unroll
        for (int h = 0; h < 2; h++) {
            const int rloc = wm * 32 + mt * 16 + (lane >> 2) + 8 * h;
            const int grow = row0 + rloc;
            const int rid  = ids[grow];
            const float dval = g_diag[grow];
            float rs = 0.f, rsm = 0.f, re = 0.f;
            #pragma unroll
            for (int nt = 0; nt < 8; nt++) {
                #pragma unroll
                for (int cc = 0; cc < 2; cc++) {
                    float s = acc[mt][nt][2 * h + cc];
                    int cloc = wn * 64 + nt * 8 + (lane & 3) * 2 + cc;
                    if (rid == s_idc[cloc]) {
                        if (grow == col0 + cloc) s = dval;   // exact diagonal
                        rsm += s;
                        float e = __expf((s - 1.0f) * INV_TAU);
                        re += e;
                        atomicAdd(&s_cexp[cloc], e);
                    }
                    rs += s;
                }
            }
            atomicAdd(&s_rexp[rloc],  re);
            atomicAdd(&s_rsum[rloc],  rs);
            atomicAdd(&s_rsame[rloc], rsm);
        }
    }
    __syncthreads();

    if (tid < 128) {
        atomicAdd(&g_rowexp[row0 + tid],  s_rexp[tid]);
        atomicAdd(&g_rowsum[row0 + tid],  s_rsum[tid]);
        atomicAdd(&g_rowsame[row0 + tid], s_rsame[tid]);
        atomicAdd(&g_colexp[col0 + tid],  s_cexp[tid]);
    }
}

// ---------------- per-row CE, segment sums, triplet (block-reduced) ----------------
__global__ void finalize_kernel(const int* __restrict__ ids) {
    __shared__ float sh_segv[NS];
    __shared__ float sh_segt[NS];
    const int tid = threadIdx.x;
    if (tid < NS) { sh_segv[tid] = 0.f; sh_segt[tid] = 0.f; }
    __syncthreads();

    int i = blockIdx.x * blockDim.x + tid;
    float tri_v = 0.f, tri_n = 0.f;
    if (i < BN) {
        int id = ids[i];
        float dl = g_diag[i] * INV_TAU;
        float cev = logf(g_rowexp[i]) + INV_TAU - dl;
        float cet = logf(g_colexp[i]) + INV_TAU - dl;
        atomicAdd(&sh_segv[id], cev);
        atomicAdd(&sh_segt[id], cet);

        float cnt = g_cnt[id];
        float pos_cnt = cnt - 1.0f;
        float neg_cnt = (float)BN - cnt;
        float pos_mean = (g_rowsame[i] - g_diag[i]) / fmaxf(pos_cnt, 1.0f);
        float neg_mean = (g_rowsum[i] - g_rowsame[i]) / fmaxf(neg_cnt, 1.0f);
        float tri = fmaxf(neg_mean - pos_mean + MARGIN, 0.0f);
        bool valid = (pos_cnt > 0.0f) && (neg_cnt > 0.0f);
        tri_v = valid ? tri : 0.0f;
        tri_n = valid ? 1.0f : 0.0f;
    }
    #pragma unroll
    for (int o = 16; o > 0; o >>= 1) {
        tri_v += __shfl_xor_sync(0xffffffffu, tri_v, o);
        tri_n += __shfl_xor_sync(0xffffffffu, tri_n, o);
    }
    if ((tid & 31) == 0) {
        atomicAdd(&g_tri[0], tri_v);
        atomicAdd(&g_tri[1], tri_n);
    }
    __syncthreads();
    if (tid < NS) {
        atomicAdd(&g_segv[tid], sh_segv[tid]);
        atomicAdd(&g_segt[tid], sh_segt[tid]);
    }
}

__global__ void combine_kernel(float* __restrict__ out) {
    __shared__ float sv[NS], sn[NS];
    int s = threadIdx.x;
    float cnt = g_cnt[s];
    bool valid = cnt >= 2.0f;
    float per = (g_segv[s] + g_segt[s]) / (2.0f * fmaxf(cnt, 1.0f));
    sv[s] = valid ? per : 0.0f;
    sn[s] = valid ? 1.0f : 0.0f;
    __syncthreads();
    if (s == 0) {
        float S = 0.f, N = 0.f;
        for (int i = 0; i < NS; i++) { S += sv[i]; N += sn[i]; }
        float loss_infonce = S / fmaxf(N, 1.0f);
        float loss_triplet = g_tri[0] / fmaxf(g_tri[1], 1.0f);
        out[0] = loss_infonce + loss_triplet;
    }
}

extern "C" void kernel_launch(void* const* d_in, const int* in_sizes, int n_in,
                              void* d_out, int out_size) {
    const float* species = (const float*)d_in[0];
    const float* text    = (const float*)d_in[1];
    const int*   ids     = (const int*)d_in[2];
    float* out = (float*)d_out;

    cudaFuncSetAttribute(gemm_kernel,
                         cudaFuncAttributeMaxDynamicSharedMemorySize, SMEM_DYN);

    zero_kernel<<<82, 512>>>();
    convert_kernel<<<(BN * DD / 4 + 255) / 256, 256>>>(species, text);
    diag_count_kernel<<<BN / 8, 256>>>(species, text, ids);
    dim3 grid(BN / 128, BN / 128);
    gemm_kernel<<<grid, 256, SMEM_DYN>>>(ids);
    finalize_kernel<<<BN / 256, 256>>>(ids);
    combine_kernel<<<1, NS>>>(out);
}